// round 12
// baseline (speedup 1.0000x reference)
#include <cuda_runtime.h>
#include <cstdint>

// ---------------------------------------------------------------------------
// PConvLinear, warp-specialized producer/consumer, fp16 mma.sync m16n8k16.
//   out[p,o] = bias[o] + sum_f P[p,f] * W[o,f],  f = c*16 + m
//   P[p, c*16+m] = sum_{k<16} feat[p,k,c] * wn[p,k,m]
// 256 thr: warps 0-3 consumers (64p x 32o GEMM each), warps 4-7 producers
// (16 points each: gather + pconv). P double-buffered; counted named
// barriers PD/CD per buffer. Producer warps independent (no cross-warp A).
// A layout: [khalf region][c-row r: 1024B][slot 16B], slot = pt^(r&7)^(r>>3)
//   -> conflict-free STS and ldsm. 2 CTAs/SM.
// ---------------------------------------------------------------------------

#define NPTS 120000
#define NB   60000
#define TPB  64
#define THREADS 256
#define GRID (NPTS / TPB)      // 1875

#define PROWB 528
#define PBUFB (64 * PROWB)     // 33792 per P buffer
#define OFF_A (2 * PBUFB)      // 67584
#define AREG  16416            // A region stride (16KB + 32B pad)
#define SMEM_BYTES (OFF_A + 2 * AREG)   // 100416 -> 2 CTAs/SM

// W fragments: [fs 80(+1 pad)][wn4 4][q*128 + l*4]
__device__ uint32_t Wfrag[81 * 1024];

__device__ __forceinline__ uint32_t smem_u32(const void* p) {
    uint32_t a;
    asm("{ .reg .u64 t; cvta.to.shared.u64 t, %1; cvt.u32.u64 %0, t; }"
        : "=r"(a) : "l"(p));
    return a;
}
__device__ __forceinline__ uint32_t pack_f16x2(float lo, float hi) {
    uint32_t r;
    asm("cvt.rn.f16x2.f32 %0, %1, %2;" : "=r"(r) : "f"(hi), "f"(lo));
    return r;
}
__device__ __forceinline__ void ldsm4(uint32_t r[4], uint32_t addr) {
    asm volatile("ldmatrix.sync.aligned.m8n8.x4.shared.b16 {%0,%1,%2,%3}, [%4];"
                 : "=r"(r[0]), "=r"(r[1]), "=r"(r[2]), "=r"(r[3]) : "r"(addr));
}
__device__ __forceinline__ void mma16(float c[4], const uint32_t a[4],
                                      uint32_t b0, uint32_t b1) {
    asm volatile(
        "mma.sync.aligned.m16n8k16.row.col.f32.f16.f16.f32 "
        "{%0,%1,%2,%3}, {%4,%5,%6,%7}, {%8,%9}, {%0,%1,%2,%3};"
        : "+f"(c[0]), "+f"(c[1]), "+f"(c[2]), "+f"(c[3])
        : "r"(a[0]), "r"(a[1]), "r"(a[2]), "r"(a[3]), "r"(b0), "r"(b1));
}
#define BAR_SYNC(id)   asm volatile("bar.sync %0, 256;"   :: "r"(id) : "memory")
#define BAR_ARRIVE(id) asm volatile("bar.arrive %0, 256;" :: "r"(id) : "memory")
#define MEMBAR_CTA()   asm volatile("membar.cta;" ::: "memory")

// ---- prep: analytic fp16 B fragments of W (unchanged, proven) ----
extern "C" __global__ void __launch_bounds__(128, 1)
prep_kernel(const float* __restrict__ W) {
    const int bg = blockIdx.x;           // fs = g*16 + s
    const int t = threadIdx.x, l = t & 31, wn4 = t >> 5;
    const int f0 = (bg >> 4) * 256 + (bg & 15) * 16 + 2 * (l & 3);
    uint32_t r[8];
    #pragma unroll
    for (int nt = 0; nt < 4; ++nt) {
        int o = wn4 * 32 + nt * 8 + (l >> 2);
        const float* wr = W + (size_t)o * 1072;
        float v0 = (f0     < 1072) ? wr[f0]     : 0.f;
        float v1 = (f0 + 1 < 1072) ? wr[f0 + 1] : 0.f;
        float v2 = (f0 + 8 < 1072) ? wr[f0 + 8] : 0.f;
        float v3 = (f0 + 9 < 1072) ? wr[f0 + 9] : 0.f;
        r[nt * 2 + 0] = pack_f16x2(v0, v1);
        r[nt * 2 + 1] = pack_f16x2(v2, v3);
    }
    uint32_t* dst = Wfrag + (bg * 4 + wn4) * 256 + l * 4;
    *(uint4*)dst         = make_uint4(r[0], r[1], r[2], r[3]);
    *(uint4*)(dst + 128) = make_uint4(r[4], r[5], r[6], r[7]);
}

// ---- main ----
extern "C" __global__ void __launch_bounds__(THREADS, 2)
pcl_kernel(const float* __restrict__ xin,   // [2,60000,64]
           const int*   __restrict__ nbr,   // [2,60000,16]
           const float* __restrict__ wng,   // [2,60000,16,16]
           const float* __restrict__ addf,  // [2,60000,16,3]
           const float* __restrict__ bias,  // [128]
           float*       __restrict__ out)   // [2,60000,128]
{
    extern __shared__ __align__(16) char smc[];
    const uint32_t smb = smem_u32(smc);
    const int t    = threadIdx.x;
    const int wid  = t >> 5;
    const int l    = t & 31;
    const int base = blockIdx.x * TPB;

    if (wid < 4) {
        // ===================== CONSUMER: warps 0-3 =====================
        const int wn4 = wid;
        float acc[4][4][4];
        #pragma unroll
        for (int i = 0; i < 4; ++i)
            #pragma unroll
            for (int j = 0; j < 4; ++j)
                #pragma unroll
                for (int q = 0; q < 4; ++q) acc[i][j][q] = 0.f;

        // bias for this thread's 4 output pairs (fixed o per nt)
        float2 bv[4];
        #pragma unroll
        for (int nt = 0; nt < 4; ++nt)
            bv[nt] = *(const float2*)(bias + wn4 * 32 + nt * 8 + 2 * (l & 3));

        const uint32_t* wf0 = Wfrag + wn4 * 256 + l * 4;
        uint4 u0c = *(const uint4*)wf0;
        uint4 u1c = *(const uint4*)(wf0 + 128);

        const uint32_t arow = smb + (uint32_t)((l & 15) * PROWB + (l >> 4) * 16);

        for (int g = 0; g < 5; ++g) {
            const int b = g & 1;
            BAR_SYNC(1 + b);                    // wait produce-done(g)
            const uint32_t pbase = arow + (uint32_t)(b * PBUFB);
            #pragma unroll 4
            for (int s = 0; s < 16; ++s) {
                const uint32_t* wfn = wf0 + (size_t)(g * 16 + s + 1) * 1024;
                uint4 u0n = *(const uint4*)wfn;
                uint4 u1n = *(const uint4*)(wfn + 128);
                uint32_t a[4][4];
                #pragma unroll
                for (int mt = 0; mt < 4; ++mt)
                    ldsm4(a[mt], pbase + (uint32_t)(mt * 16 * PROWB + s * 32));
                #pragma unroll
                for (int mt = 0; mt < 4; ++mt) {
                    mma16(acc[mt][0], a[mt], u0c.x, u0c.y);
                    mma16(acc[mt][1], a[mt], u0c.z, u0c.w);
                    mma16(acc[mt][2], a[mt], u1c.x, u1c.y);
                    mma16(acc[mt][3], a[mt], u1c.z, u1c.w);
                }
                u0c = u0n; u1c = u1n;
            }
            BAR_ARRIVE(3 + b);                  // consume-done(g)
        }

        // epilogue: this warp writes all 64 rows x its 32 outputs
        #pragma unroll
        for (int mt = 0; mt < 4; ++mt) {
            int r = mt * 16 + (l >> 2);
            #pragma unroll
            for (int nt = 0; nt < 4; ++nt) {
                int o = wn4 * 32 + nt * 8 + 2 * (l & 3);
                int pid = base + r;
                *(float2*)(out + (size_t)pid * 128 + o) =
                    make_float2(acc[mt][nt][0] + bv[nt].x,
                                acc[mt][nt][1] + bv[nt].y);
                *(float2*)(out + (size_t)(pid + 8) * 128 + o) =
                    make_float2(acc[mt][nt][2] + bv[nt].x,
                                acc[mt][nt][3] + bv[nt].y);
            }
        }
    } else {
        // ===================== PRODUCER: warps 4-7 =====================
        const int pw  = wid - 4;            // owns points pw*16 .. +16
        const int gw  = l & 3;              // gather: channel quad
        const int gkp = l >> 2;             // gather: k pair 0-7

        // pconv B fragments for own 16 points (m16n8k16 B layout)
        uint32_t bw[16][2][2];
        {
            const int c2 = 2 * (l & 3);
            const int nl = l >> 2;
            #pragma unroll 4
            for (int j = 0; j < 16; ++j) {
                const float* wp = wng + (size_t)(base + pw * 16 + j) * 256;
                #pragma unroll
                for (int h = 0; h < 2; ++h) {
                    int m = h * 8 + nl;
                    bw[j][h][0] = pack_f16x2(wp[c2 * 16 + m],
                                             wp[(c2 + 1) * 16 + m]);
                    bw[j][h][1] = pack_f16x2(wp[(c2 + 8) * 16 + m],
                                             wp[(c2 + 9) * 16 + m]);
                }
            }
        }

        // pconv ldsm role constants
        const int r_  = l & 15;
        const int hi_ = l >> 4;
        const int s0  = (r_ & 7) ^ (r_ >> 3);            // slot xor key
        const uint32_t aLdBase = smb + (uint32_t)(OFF_A + hi_ * AREG + r_ * 1024);
        const int rr  = l >> 2;              // pconv STS: f-row
        const int mc  = 2 * (l & 3);

        // gather STS base (region + word-in-chunk fixed per thread)
        char* gBase = smc + OFF_A + (gkp >> 2) * AREG + (gkp & 3) * 4;

        for (int g = 0; g < 5; ++g) {
            const int b = g & 1;

            // ---- gather own 16 points into A ----
            #pragma unroll 4
            for (int j = 0; j < 16; ++j) {
                int ptl = pw * 16 + j;
                int pid = base + ptl;
                float va[4], vb[4];
                if (g < 4) {
                    int2 nb = *(const int2*)(nbr + (size_t)pid * 16 + 2 * gkp);
                    int brow = (pid >= NB) ? NB : 0;
                    float4 A4 = *(const float4*)(xin + (size_t)(brow + nb.x) * 64
                                                 + g * 16 + gw * 4);
                    float4 B4 = *(const float4*)(xin + (size_t)(brow + nb.y) * 64
                                                 + g * 16 + gw * 4);
                    va[0] = A4.x; va[1] = A4.y; va[2] = A4.z; va[3] = A4.w;
                    vb[0] = B4.x; vb[1] = B4.y; vb[2] = B4.z; vb[3] = B4.w;
                } else {
                    #pragma unroll
                    for (int q = 0; q < 4; ++q) { va[q] = 0.f; vb[q] = 0.f; }
                    if (gw == 0) {
                        const float* a0 = addf + ((size_t)pid * 16 + 2 * gkp) * 3;
                        va[0] = a0[0]; va[1] = a0[1]; va[2] = a0[2];
                        vb[0] = a0[3]; vb[1] = a0[4]; vb[2] = a0[5];
                    }
                }
                #pragma unroll
                for (int cw = 0; cw < 4; ++cw) {
                    int r = gw * 4 + cw;
                    int slot = ptl ^ (r & 7) ^ (r >> 3);
                    *(uint32_t*)(gBase + r * 1024 + slot * 16) =
                        pack_f16x2(va[cw], vb[cw]);
                }
            }
            __syncwarp();

            // P buffer free? (consumer done with it two groups ago)
            if (g >= 2) BAR_SYNC(3 + b);

            // ---- pconv own 16 points -> P[b] ----
            #pragma unroll 4
            for (int j = 0; j < 16; ++j) {
                int ptl = pw * 16 + j;
                uint32_t a[4];
                ldsm4(a, aLdBase + (uint32_t)((ptl ^ s0) * 16));
                char* prow = smc + b * PBUFB + ptl * PROWB;
                #pragma unroll
                for (int h = 0; h < 2; ++h) {
                    float c[4] = {0.f, 0.f, 0.f, 0.f};
                    mma16(c, a, bw[j][h][0], bw[j][h][1]);
                    int fl = rr * 16 + h * 8 + mc;
                    *(uint32_t*)(prow + fl * 2)         = pack_f16x2(c[0], c[1]);
                    *(uint32_t*)(prow + (fl + 128) * 2) = pack_f16x2(c[2], c[3]);
                }
            }
            MEMBAR_CTA();
            BAR_ARRIVE(1 + b);                  // produce-done(g)
        }
    }
}

extern "C" void kernel_launch(void* const* d_in, const int* in_sizes, int n_in,
                              void* d_out, int out_size) {
    const float* xin  = (const float*)d_in[0];
    const int*   nbr  = (const int*)d_in[1];
    const float* wng  = (const float*)d_in[2];
    const float* addf = (const float*)d_in[3];
    const float* W    = (const float*)d_in[4];
    const float* bias = (const float*)d_in[5];
    float*       out  = (float*)d_out;

    cudaFuncSetAttribute(pcl_kernel,
                         cudaFuncAttributeMaxDynamicSharedMemorySize, SMEM_BYTES);

    prep_kernel<<<80, 128>>>(W);
    pcl_kernel<<<GRID, THREADS, SMEM_BYTES>>>(xin, nbr, wng, addf, bias, out);
}